// round 2
// baseline (speedup 1.0000x reference)
#include <cuda_runtime.h>
#include <cuda_bf16.h>
#include <cuda_fp8.h>
#include <cstdint>

// ============================================================================
// Problem constants / scratch
// ============================================================================

static constexpr int M_DIM = 2048;
static constexpr int N_DIM = 4096;
static constexpr int K_DIM = 4096;
static constexpr float FP8_MAX_F = 448.0f;

__device__ __align__(1024) uint8_t g_qx[(size_t)M_DIM * K_DIM];
__device__ __align__(1024) uint8_t g_qw[(size_t)N_DIM * K_DIM];
__device__ unsigned int g_amax_bits[2];
__device__ float g_scales[4];  // [0]=mult_x, [1]=mult_w, [2]=alpha

// ============================================================================
// Quantization kernels
// ============================================================================

__global__ void init_kernel() {
    g_amax_bits[0] = 0u;
    g_amax_bits[1] = 0u;
}

__global__ void amax_kernel(const float* __restrict__ p, int n4, int slot) {
    float m = 0.0f;
    int stride = gridDim.x * blockDim.x;
    for (int i = blockIdx.x * blockDim.x + threadIdx.x; i < n4; i += stride) {
        float4 v = reinterpret_cast<const float4*>(p)[i];
        m = fmaxf(m, fmaxf(fmaxf(fabsf(v.x), fabsf(v.y)),
                           fmaxf(fabsf(v.z), fabsf(v.w))));
    }
    #pragma unroll
    for (int o = 16; o > 0; o >>= 1)
        m = fmaxf(m, __shfl_xor_sync(0xFFFFFFFFu, m, o));
    __shared__ float sm[32];
    if ((threadIdx.x & 31) == 0) sm[threadIdx.x >> 5] = m;
    __syncthreads();
    if (threadIdx.x < 32) {
        m = (threadIdx.x < (blockDim.x >> 5)) ? sm[threadIdx.x] : 0.0f;
        #pragma unroll
        for (int o = 16; o > 0; o >>= 1)
            m = fmaxf(m, __shfl_xor_sync(0xFFFFFFFFu, m, o));
        if (threadIdx.x == 0)
            atomicMax(&g_amax_bits[slot], __float_as_uint(m));
    }
}

__global__ void scales_kernel() {
    float ax = fmaxf(__uint_as_float(g_amax_bits[0]), 1e-12f);
    float aw = fmaxf(__uint_as_float(g_amax_bits[1]), 1e-12f);
    float sx = FP8_MAX_F / ax;
    float sw = FP8_MAX_F / aw;
    g_scales[0] = sx;
    g_scales[1] = sw;
    g_scales[2] = (1.0f / sx) * (1.0f / sw);
}

__global__ void quant_kernel(const float* __restrict__ src,
                             uint32_t* __restrict__ dst, int n4, int slot) {
    float s = g_scales[slot];
    int stride = gridDim.x * blockDim.x;
    for (int i = blockIdx.x * blockDim.x + threadIdx.x; i < n4; i += stride) {
        float4 v = reinterpret_cast<const float4*>(src)[i];
        float2 lo = make_float2(v.x * s, v.y * s);
        float2 hi = make_float2(v.z * s, v.w * s);
        __nv_fp8x2_storage_t plo = __nv_cvt_float2_to_fp8x2(lo, __NV_SATFINITE, __NV_E4M3);
        __nv_fp8x2_storage_t phi = __nv_cvt_float2_to_fp8x2(hi, __NV_SATFINITE, __NV_E4M3);
        dst[i] = (uint32_t)plo | ((uint32_t)phi << 16);
    }
}

// ============================================================================
// FP8 GEMM via mma.sync (portable path — tcgen05 unavailable on base sm_103
// target used by the harness). D[M,N] = Qx[M,K] * Qw[N,K]^T, fp32 accum.
// Epilogue: out = D * alpha + bias.
// ============================================================================

static constexpr int BM = 128;
static constexpr int BN = 128;
static constexpr int BK = 64;        // fp8 bytes of K per stage
static constexpr int STAGES = 4;
static constexpr int GEMM_THREADS = 256;   // 8 warps: 2 (M) x 4 (N)

// 80-byte row pitch: 64B of data per row, pitch chosen so the 8 ldmatrix row
// segments (16B each) cover all 32 banks exactly once (20*r mod 32 distinct).
static constexpr int PITCH = 80;
static constexpr int A_BYTES = BM * PITCH;          // 10240
static constexpr int STAGE_BYTES = 2 * A_BYTES;     // A + B = 20480
static constexpr int GEMM_SMEM = STAGES * STAGE_BYTES;  // 81920

__device__ __forceinline__ uint32_t smem_u32(const void* p) {
    uint32_t a;
    asm("{ .reg .u64 t; cvta.to.shared.u64 t, %1; cvt.u32.u64 %0, t; }"
        : "=r"(a) : "l"(p));
    return a;
}

__device__ __forceinline__ void cp_async16(uint32_t dst, const void* src) {
    asm volatile("cp.async.cg.shared.global [%0], [%1], 16;"
                 :: "r"(dst), "l"(src) : "memory");
}

#define CP_COMMIT()  asm volatile("cp.async.commit_group;" ::: "memory")
#define CP_WAIT(n)   asm volatile("cp.async.wait_group %0;" :: "n"(n) : "memory")

__device__ __forceinline__ void ldsm_x4(uint32_t* r, uint32_t addr) {
    asm volatile("ldmatrix.sync.aligned.m8n8.x4.shared.b16 {%0,%1,%2,%3}, [%4];"
                 : "=r"(r[0]), "=r"(r[1]), "=r"(r[2]), "=r"(r[3]) : "r"(addr));
}

__device__ __forceinline__ void mma_e4m3(float* d, const uint32_t* a,
                                         uint32_t b0, uint32_t b1) {
    asm volatile(
        "mma.sync.aligned.m16n8k32.row.col.f32.e4m3.e4m3.f32 "
        "{%0,%1,%2,%3}, {%4,%5,%6,%7}, {%8,%9}, {%0,%1,%2,%3};"
        : "+f"(d[0]), "+f"(d[1]), "+f"(d[2]), "+f"(d[3])
        : "r"(a[0]), "r"(a[1]), "r"(a[2]), "r"(a[3]), "r"(b0), "r"(b1));
}

__global__ __launch_bounds__(GEMM_THREADS, 2)
void gemm_fp8_kernel(const uint8_t* __restrict__ qa,
                     const uint8_t* __restrict__ qb,
                     const float* __restrict__ bias,
                     float* __restrict__ out,
                     int Mdim, int Ndim, int Kdim) {
    extern __shared__ __align__(1024) uint8_t smem[];
    const uint32_t sbase = smem_u32(smem);

    const int tid  = threadIdx.x;
    const int wid  = tid >> 5;
    const int lane = tid & 31;
    const int wm   = wid >> 2;   // 0..1
    const int wn   = wid & 3;    // 0..3

    const int m0 = blockIdx.y * BM;
    const int n0 = blockIdx.x * BN;

    // ---- cp.async source/dest precompute (4 chunks per thread per stage) ----
    // chunks 0..511: A (row = c>>2, 16B-chunk = c&3); 512..1023: B.
    const uint8_t* gA = qa + (size_t)m0 * Kdim;
    const uint8_t* gB = qb + (size_t)n0 * Kdim;

    // ---- ldmatrix address offsets (within a stage) ----
    const int lrow  = (lane & 7) | (((lane >> 3) & 1) << 3);  // 0..15
    const int lcolb = ((lane >> 4) & 1) << 4;                 // 0 or 16
    uint32_t a_off[4], b_off[2];
    #pragma unroll
    for (int mi = 0; mi < 4; mi++)
        a_off[mi] = (uint32_t)((wm * 64 + mi * 16 + lrow) * PITCH + lcolb);
    #pragma unroll
    for (int p = 0; p < 2; p++)
        b_off[p] = (uint32_t)(A_BYTES + (wn * 32 + p * 16 + lrow) * PITCH + lcolb);

    float acc[4][4][4];
    #pragma unroll
    for (int mi = 0; mi < 4; mi++)
        #pragma unroll
        for (int ni = 0; ni < 4; ni++)
            #pragma unroll
            for (int r = 0; r < 4; r++)
                acc[mi][ni][r] = 0.0f;

    const int kchunks = Kdim / BK;  // 64

    auto issue_stage = [&](int s) {
        const uint32_t stg = sbase + (uint32_t)(s % STAGES) * STAGE_BYTES;
        const int k0 = s * BK;
        #pragma unroll
        for (int it = 0; it < 4; it++) {
            int c = tid + it * GEMM_THREADS;
            int row = (c & 511) >> 2;
            int ch  = c & 3;
            if (c < 512) {
                cp_async16(stg + row * PITCH + ch * 16,
                           gA + (size_t)row * Kdim + k0 + ch * 16);
            } else {
                cp_async16(stg + A_BYTES + row * PITCH + ch * 16,
                           gB + (size_t)row * Kdim + k0 + ch * 16);
            }
        }
        CP_COMMIT();
    };

    // prefetch STAGES-1 stages
    issue_stage(0);
    issue_stage(1);
    issue_stage(2);

    for (int s = 0; s < kchunks; s++) {
        CP_WAIT(2);
        __syncthreads();

        if (s + 3 < kchunks) issue_stage(s + 3);

        const uint32_t stg = sbase + (uint32_t)(s % STAGES) * STAGE_BYTES;

        #pragma unroll
        for (int kk = 0; kk < 2; kk++) {
            uint32_t af[4][4], bf[2][4];
            #pragma unroll
            for (int mi = 0; mi < 4; mi++)
                ldsm_x4(af[mi], stg + a_off[mi] + kk * 32);
            #pragma unroll
            for (int p = 0; p < 2; p++)
                ldsm_x4(bf[p], stg + b_off[p] + kk * 32);

            #pragma unroll
            for (int mi = 0; mi < 4; mi++)
                #pragma unroll
                for (int ni = 0; ni < 4; ni++) {
                    int p = ni >> 1, o = ni & 1;
                    mma_e4m3(acc[mi][ni], af[mi], bf[p][o], bf[p][2 + o]);
                }
        }
        __syncthreads();
    }

    // ---- epilogue: out = acc * alpha + bias ----
    const float alpha = g_scales[2];
    const int g = lane >> 2;      // 0..7
    const int q = lane & 3;       // 0..3

    #pragma unroll
    for (int mi = 0; mi < 4; mi++) {
        #pragma unroll
        for (int ni = 0; ni < 4; ni++) {
            int col = n0 + wn * 32 + ni * 8 + q * 2;
            float2 bv = *reinterpret_cast<const float2*>(bias + col);
            int row0 = m0 + wm * 64 + mi * 16 + g;
            float2 o0, o1;
            o0.x = acc[mi][ni][0] * alpha + bv.x;
            o0.y = acc[mi][ni][1] * alpha + bv.y;
            o1.x = acc[mi][ni][2] * alpha + bv.x;
            o1.y = acc[mi][ni][3] * alpha + bv.y;
            *reinterpret_cast<float2*>(out + (size_t)row0 * Ndim + col) = o0;
            *reinterpret_cast<float2*>(out + (size_t)(row0 + 8) * Ndim + col) = o1;
        }
    }
}

// ============================================================================
// kernel_launch
// ============================================================================

extern "C" void kernel_launch(void* const* d_in, const int* in_sizes, int n_in,
                              void* d_out, int out_size) {
    const float* x    = (const float*)d_in[0];
    const float* w    = (const float*)d_in[1];
    const float* bias = (const float*)d_in[2];
    float* out = (float*)d_out;

    int N = in_sizes[2];
    int K = in_sizes[1] / N;
    int M = in_sizes[0] / K;

    uint8_t *qx = nullptr, *qw = nullptr;
    cudaGetSymbolAddress((void**)&qx, g_qx);
    cudaGetSymbolAddress((void**)&qw, g_qw);

    int n4x = (M * K) / 4;
    int n4w = (N * K) / 4;

    init_kernel<<<1, 1>>>();
    amax_kernel<<<2048, 256>>>(x, n4x, 0);
    amax_kernel<<<2048, 256>>>(w, n4w, 1);
    scales_kernel<<<1, 1>>>();
    quant_kernel<<<4096, 256>>>(x, (uint32_t*)qx, n4x, 0);
    quant_kernel<<<8192, 256>>>(w, (uint32_t*)qw, n4w, 1);

    cudaFuncSetAttribute(gemm_fp8_kernel,
                         cudaFuncAttributeMaxDynamicSharedMemorySize, GEMM_SMEM);
    dim3 grid(N / BN, M / BM);
    gemm_fp8_kernel<<<grid, GEMM_THREADS, GEMM_SMEM>>>(qx, qw, bias, out, M, N, K);
}